// round 11
// baseline (speedup 1.0000x reference)
#include <cuda_runtime.h>
#include <math.h>
#include <stdint.h>

// Problem constants (Gemma attention, B=2,S=2048,HID=2048,H=8,KH=1,D=256)
#define BB   2
#define SS   2048
#define HID_ 2048
#define HH   8
#define DD   256
#define NQKV 2560

typedef long long ll;

// Panel: 128 rows x 64 int8 (k64), slice1 8KB | slice2 8KB, SW64 swizzle.
#define PAN   16384
#define STG   (2 * PAN)          // A panel + B panel
#define NST   4
#define GSMEM (NST * STG)        // 131072

// ---------------------------------------------------------------------------
// Scratch (__device__ globals — allocation-free)
// ---------------------------------------------------------------------------
__device__ float g_qkv[(size_t)BB * SS * NQKV];
__device__ float g_bqkv[NQKV];
__device__ float g_vT[(size_t)BB * DD * SS];
__device__ float g_ctx[(size_t)BB * SS * HH * DD];

__device__ __align__(128) char g_hidpan [(size_t)32 * 32 * PAN];        // 16.8 MB
__device__ __align__(128) char g_wqkvpan[(size_t)20 * 32 * PAN];        // 10.5 MB
__device__ __align__(128) char g_wopan  [(size_t)16 * 32 * PAN];        // 8.4 MB
__device__ __align__(128) char g_qpan   [(size_t)BB * HH * 16 * 4 * PAN];
__device__ __align__(128) char g_kpan   [(size_t)BB * 16 * 4 * PAN];
__device__ __align__(128) char g_vtpan  [(size_t)4 * 32 * PAN];
__device__ __align__(128) char g_attnpan[(size_t)BB * HH * 16 * 32 * PAN]; // 134 MB
__device__ __align__(128) char g_ctxpan [(size_t)32 * 32 * PAN];

__device__ float g_sh[BB * SS];
__device__ float g_sw[NQKV];
__device__ float g_swo[HID_];
__device__ float g_sq[BB * SS * HH];
__device__ float g_sk[BB * SS];
__device__ float g_svt[BB * DD];
__device__ float g_sa[BB * HH * SS];
__device__ float g_sc[BB * SS];

// ---------------------------------------------------------------------------
// PTX helpers
// ---------------------------------------------------------------------------
__device__ __forceinline__ uint32_t smem_u32(const void* p) {
    uint32_t a;
    asm("{ .reg .u64 t; cvta.to.shared.u64 t, %1; cvt.u32.u64 %0, t; }"
        : "=r"(a) : "l"(p));
    return a;
}

#define MBAR_INIT(addr, cnt) \
    asm volatile("mbarrier.init.shared.b64 [%0], %1;" :: "r"(addr), "r"(cnt) : "memory")
#define MBAR_ARRIVE(addr) \
    asm volatile("mbarrier.arrive.shared.b64 _, [%0];" :: "r"(addr) : "memory")
#define MBAR_EXPECT_TX(addr, bytes) \
    asm volatile("mbarrier.arrive.expect_tx.shared.b64 _, [%0], %1;" \
                 :: "r"(addr), "r"(bytes) : "memory")

#define WAITP(mbar_addr, parity) do {                                              \
    uint32_t _mbar = (uint32_t)(mbar_addr);                                        \
    uint32_t _par  = (uint32_t)(parity);                                           \
    uint32_t _done;                                                                \
    asm volatile(                                                                  \
        "{\n\t.reg .pred p;\n\t"                                                   \
        "mbarrier.try_wait.parity.acquire.cta.shared::cta.b64 p, [%1], %2;\n\t"    \
        "selp.b32 %0, 1, 0, p;\n\t}"                                               \
        : "=r"(_done) : "r"(_mbar), "r"(_par) : "memory");                         \
    if (!_done) {                                                                  \
        asm volatile(                                                              \
            "{\n\t.reg .pred P1;\n\t"                                              \
            "WAIT_LOOP_%=:\n\t"                                                    \
            "mbarrier.try_wait.parity.acquire.cta.shared::cta.b64 P1, [%0], %1, 0x989680;\n\t" \
            "@P1 bra.uni WAIT_DONE_%=;\n\t"                                        \
            "bra.uni WAIT_LOOP_%=;\n\t"                                            \
            "WAIT_DONE_%=:\n\t}"                                                   \
            :: "r"(_mbar), "r"(_par) : "memory");                                  \
    }                                                                              \
} while (0)

__device__ __forceinline__ void bulkcp(uint32_t dst, const void* src,
                                       uint32_t bytes, uint32_t mbar) {
    asm volatile(
        "cp.async.bulk.shared::cluster.global.mbarrier::complete_tx::bytes "
        "[%0], [%1], %2, [%3];"
        :: "r"(dst), "l"(src), "r"(bytes), "r"(mbar) : "memory");
}

__device__ __forceinline__ void ldm_x4(uint32_t* r, uint32_t addr) {
    asm volatile("ldmatrix.sync.aligned.m8n8.x4.shared.b16 {%0,%1,%2,%3}, [%4];"
                 : "=r"(r[0]), "=r"(r[1]), "=r"(r[2]), "=r"(r[3]) : "r"(addr));
}

__device__ __forceinline__ void imma(int* c, const uint32_t* a,
                                     uint32_t b0, uint32_t b1) {
    asm volatile(
        "mma.sync.aligned.m16n8k32.row.col.s32.s8.s8.s32 "
        "{%0,%1,%2,%3}, {%4,%5,%6,%7}, {%8,%9}, {%0,%1,%2,%3};"
        : "+r"(c[0]), "+r"(c[1]), "+r"(c[2]), "+r"(c[3])
        : "r"(a[0]), "r"(a[1]), "r"(a[2]), "r"(a[3]), "r"(b0), "r"(b1));
}

__device__ __forceinline__ void quant2(float a, int8_t& o1, int8_t& o2) {
    int a1 = __float2int_rn(a);
    a1 = max(-127, min(127, a1));
    int a2 = __float2int_rn((a - (float)a1) * 256.0f);
    a2 = max(-127, min(127, a2));
    o1 = (int8_t)a1;
    o2 = (int8_t)a2;
}

// SW64-swizzled byte offset within a panel slice (128 rows x 64B).
__device__ __forceinline__ uint32_t pan_off(int rin, int cin) {
    return (uint32_t)(rin * 64 + ((((cin >> 4) ^ ((rin >> 1) & 3))) << 4)
                      + (cin & 15));
}

// ===========================================================================
// Panelized 2-slice int8 NT GEMM (3-term):
//   C = alpha*sA_r*sB_c*(A1B1 + (A1B2 + A2B1)*2^-8) + bias
//   CTA 128x128xk64, 512 thr (16 warps, warp 32x32), 4-stage bulk pipeline.
// ===========================================================================
__global__ __launch_bounds__(512, 1)
void igemm(const char* __restrict__ Ap, const char* __restrict__ Bp,
           const float* __restrict__ sA, const float* __restrict__ sB,
           const float* __restrict__ bias, float* __restrict__ C,
           int K, int ldc, int Hdim,
           ll sAb, ll sAh, ll sBb, ll sBh, ll sCb, ll sCh,
           ll sab, ll sah, ll sar, ll sbb, ll sbh, ll sbr,
           float alpha)
{
    extern __shared__ __align__(128) char dsm[];
    __shared__ __align__(8) uint64_t mb[2 * NST];
    const uint32_t sbase = smem_u32(dsm);
    const uint32_t mbF = smem_u32(&mb[0]);
    const uint32_t mbE = smem_u32(&mb[NST]);

    const int tid  = threadIdx.x;
    const int wid  = tid >> 5;
    const int lane = tid & 31;
    const int wm   = wid >> 2;          // 0..3 (32-row band)
    const int wn   = wid & 3;           // 0..3 (32-col band)

    const int z  = blockIdx.z;
    const int bz = z / Hdim;
    const int hz = z - bz * Hdim;

    const int nc = K >> 6;
    const char* aSrc = Ap + (ll)bz * sAb + (ll)hz * sAh + (ll)blockIdx.y * nc * PAN;
    const char* bSrc = Bp + (ll)bz * sBb + (ll)hz * sBh + (ll)blockIdx.x * nc * PAN;
    sA += (ll)bz * sab + (ll)hz * sah + (ll)blockIdx.y * 128 * sar;
    sB += (ll)bz * sbb + (ll)hz * sbh + (ll)blockIdx.x * 128 * sbr;

    if (tid == 0) {
#pragma unroll
        for (int s = 0; s < NST; s++) {
            MBAR_INIT(mbF + 8 * s, 1);
            MBAR_INIT(mbE + 8 * s, 512);
        }
    }
    __syncthreads();

    auto produce = [&](int c) {
        if (c >= nc || tid != 0) return;
        const int s = c & (NST - 1), r = c / NST;
        if (r > 0) WAITP(mbE + 8 * s, (r - 1) & 1);
        MBAR_EXPECT_TX(mbF + 8 * s, (uint32_t)STG);
        const uint32_t d = sbase + s * STG;
        bulkcp(d,       aSrc + (ll)c * PAN, PAN, mbF + 8 * s);
        bulkcp(d + PAN, bSrc + (ll)c * PAN, PAN, mbF + 8 * s);
    };

    int accM[2][4][4], accX[2][4][4];
#pragma unroll
    for (int i = 0; i < 2; i++)
#pragma unroll
        for (int j = 0; j < 4; j++)
#pragma unroll
            for (int r = 0; r < 4; r++) { accM[i][j][r] = 0; accX[i][j][r] = 0; }

    produce(0); produce(1); produce(2);

    const int rowloc = lane & 15;
    const int segb   = lane >> 4;
    const int xr     = (rowloc >> 1) & 3;

    for (int c = 0; c < nc; c++) {
        const int s = c & (NST - 1), r = c / NST;
        produce(c + 3);
        WAITP(mbF + 8 * s, r & 1);

        const uint32_t tb  = sbase + s * STG;
        const uint32_t aB0 = tb + wm * 2048;         // wm*32 rows * 64B
        const uint32_t bB0 = tb + PAN + wn * 2048;

#pragma unroll
        for (int ks = 0; ks < 2; ks++) {
            const uint32_t lo = (uint32_t)rowloc * 64
                              + (uint32_t)((((ks << 1) + segb) ^ xr) << 4);
            uint32_t a1[2][4], a2[2][4], b1[2][4], b2[2][4];
#pragma unroll
            for (int mt = 0; mt < 2; mt++) {
                ldm_x4(a1[mt], aB0 + mt * 1024 + lo);
                ldm_x4(a2[mt], aB0 + 8192 + mt * 1024 + lo);
            }
#pragma unroll
            for (int wv = 0; wv < 2; wv++) {
                ldm_x4(b1[wv], bB0 + wv * 1024 + lo);
                ldm_x4(b2[wv], bB0 + 8192 + wv * 1024 + lo);
            }
#pragma unroll
            for (int mt = 0; mt < 2; mt++)
#pragma unroll
                for (int j = 0; j < 4; j++)
                    imma(accM[mt][j], a1[mt], b1[j >> 1][j & 1], b1[j >> 1][2 + (j & 1)]);
#pragma unroll
            for (int mt = 0; mt < 2; mt++)
#pragma unroll
                for (int j = 0; j < 4; j++)
                    imma(accX[mt][j], a1[mt], b2[j >> 1][j & 1], b2[j >> 1][2 + (j & 1)]);
#pragma unroll
            for (int mt = 0; mt < 2; mt++)
#pragma unroll
                for (int j = 0; j < 4; j++)
                    imma(accX[mt][j], a2[mt], b1[j >> 1][j & 1], b1[j >> 1][2 + (j & 1)]);
        }
        MBAR_ARRIVE(mbE + 8 * s);
    }

    // ---- epilogue ----
    float* Cb = C + (ll)bz * sCb + (ll)hz * sCh
              + (ll)blockIdx.y * 128 * ldc + (ll)blockIdx.x * 128;
    const int colblk = blockIdx.x << 7;

#pragma unroll
    for (int mt = 0; mt < 2; mt++) {
        const int row0 = wm * 32 + mt * 16 + (lane >> 2);
#pragma unroll
        for (int hrow = 0; hrow < 2; hrow++) {
            const int row = row0 + hrow * 8;
            const float fa = alpha * sA[(ll)row * sar];
#pragma unroll
            for (int j = 0; j < 4; j++) {
                const int col = wn * 32 + j * 8 + (lane & 3) * 2;
                float v0 = (float)accM[mt][j][hrow * 2 + 0]
                         + 0x1p-8f * (float)accX[mt][j][hrow * 2 + 0];
                float v1 = (float)accM[mt][j][hrow * 2 + 1]
                         + 0x1p-8f * (float)accX[mt][j][hrow * 2 + 1];
                v0 *= fa * sB[(ll)col * sbr];
                v1 *= fa * sB[(ll)(col + 1) * sbr];
                if (bias) { v0 += bias[colblk + col]; v1 += bias[colblk + col + 1]; }
                *(float2*)(Cb + (ll)row * ldc + col) = make_float2(v0, v1);
            }
        }
    }
}

// ---------------------------------------------------------------------------
// Row quantizer -> panels + scale. Panel tile = (row0+blockIdx.x)/128.
// ---------------------------------------------------------------------------
__global__ __launch_bounds__(256)
void rowquant_pan(const float* __restrict__ x, int C, int row0,
                  char* __restrict__ pan, float* __restrict__ sc)
{
    const int rloc = blockIdx.x;
    const int rg   = rloc + row0;
    x += (ll)rloc * C;
    const int tid  = threadIdx.x;
    const int w    = tid >> 5;
    const int lane = tid & 31;
    __shared__ float red[8];

    float m = 0.f;
    for (int i = tid; i < C; i += 256) m = fmaxf(m, fabsf(x[i]));
#pragma unroll
    for (int o = 16; o; o >>= 1) m = fmaxf(m, __shfl_xor_sync(0xffffffffu, m, o));
    if (lane == 0) red[w] = m;
    __syncthreads();
#pragma unroll
    for (int i = 0; i < 8; i++) m = fmaxf(m, red[i]);
    m = fmaxf(m, 1e-30f);
    const float inv = 127.0f / m;
    if (tid == 0) sc[rg] = m * (1.0f / 127.0f);

    const int tile = rg >> 7, rin = rg & 127;
    char* pt = pan + ((ll)tile * (C >> 6)) * PAN;
    for (int i = tid; i < C; i += 256) {
        int8_t o1, o2;
        quant2(x[i] * inv, o1, o2);
        char* pp = pt + (ll)(i >> 6) * PAN;
        const uint32_t off = pan_off(rin, i & 63);
        pp[off]        = o1;
        pp[8192 + off] = o2;
    }
}

// ---------------------------------------------------------------------------
// RoPE + quantize + panelize: one block (128 thr) per (bs, h) row.
// Panel base per (b*Hx+h): 16 tiles x 4 chunks.
// ---------------------------------------------------------------------------
__global__ __launch_bounds__(128)
void rope_quant_pan(const float* __restrict__ src, const int* __restrict__ pos,
                    char* __restrict__ pan, float* __restrict__ sc, int Hx)
{
    const int blk = blockIdx.x;
    const int h   = blk % Hx;
    const int bs  = blk / Hx;
    const int b   = bs / SS, sI = bs % SS;
    const int t   = threadIdx.x;
    const int w   = t >> 5, lane = t & 31;
    __shared__ float red[4];

    const float p   = (float)pos[bs];
    const float ivf = __expf(-(float)t * (9.210340371976184f / 128.f));
    float sn, cs;
    sincosf(p * ivf, &sn, &cs);
    const float* xr_ = src + (ll)bs * NQKV + h * DD;
    const float x1 = xr_[t], x2 = xr_[t + 128];
    const float y1 = cs * x1 - sn * x2;
    const float y2 = sn * x1 + cs * x2;

    float m = fmaxf(fabsf(y1), fabsf(y2));
#pragma unroll
    for (int o = 16; o; o >>= 1) m = fmaxf(m, __shfl_xor_sync(0xffffffffu, m, o));
    if (lane == 0) red[w] = m;
    __syncthreads();
#pragma unroll
    for (int i = 0; i < 4; i++) m = fmaxf(m, red[i]);
    m = fmaxf(m, 1e-30f);
    const float inv = 127.0f / m;
    // scale index: q (Hx=8): b*S*H + s*H + h == blk; k (Hx=1): b*S + s == blk
    if (t == 0) sc[blk] = m * (1.0f / 127.0f);

    const int tile = sI >> 7, rin = sI & 127;
    char* pt = pan + (((ll)(b * Hx + h) * 16 + tile) * 4) * (ll)PAN;
    int8_t o1, o2;
    {
        char* pp = pt + (ll)(t >> 6) * PAN;
        const uint32_t off = pan_off(rin, t & 63);
        quant2(y1 * inv, o1, o2);
        pp[off] = o1;  pp[8192 + off] = o2;
    }
    {
        const int d = t + 128;
        char* pp = pt + (ll)(d >> 6) * PAN;
        const uint32_t off = pan_off(rin, d & 63);
        quant2(y2 * inv, o1, o2);
        pp[off] = o1;  pp[8192 + off] = o2;
    }
}

// ---------------------------------------------------------------------------
// Transpose v (qkv col 2304) -> fp32 vT (b,D,S)
// ---------------------------------------------------------------------------
__global__ void transpose_v(const float* __restrict__ qkv, float* __restrict__ vT)
{
    __shared__ float t[32][33];
    const int b  = blockIdx.z;
    const int s0 = blockIdx.x * 32;
    const int d0 = blockIdx.y * 32;
    const int tx = threadIdx.x, ty = threadIdx.y;
    const float* src = qkv + (ll)b * SS * NQKV + 2304;
#pragma unroll
    for (int i = 0; i < 32; i += 8)
        t[ty + i][tx] = src[(ll)(s0 + ty + i) * NQKV + d0 + tx];
    __syncthreads();
    float* dst = vT + (ll)b * DD * SS;
#pragma unroll
    for (int i = 0; i < 32; i += 8)
        dst[(ll)(d0 + ty + i) * SS + s0 + tx] = t[tx][ty + i];
}

// ---------------------------------------------------------------------------
// Row softmax (B,H,S,S) in place (+mask) + quantized panels (A panels).
// ---------------------------------------------------------------------------
__global__ __launch_bounds__(256)
void softmax_quant_pan(float* __restrict__ attn, const float* __restrict__ mask,
                       char* __restrict__ pan, float* __restrict__ sc)
{
    const int HSrows = HH * SS;
    const ll r = blockIdx.x;
    const int b = (int)(r / HSrows);
    float* row = attn + r * (ll)SS;
    const float* mrow = mask + (ll)b * SS;

    const int tid  = threadIdx.x;
    const int w    = tid >> 5;
    const int lane = tid & 31;
    __shared__ float red[8];

    float v[8];
    float mx = -1e30f;
#pragma unroll
    for (int i = 0; i < 8; i++) {
        const int c = tid + i * 256;
        const float x = row[c] + mrow[c];
        v[i] = x;
        mx = fmaxf(mx, x);
    }
#pragma unroll
    for (int o = 16; o; o >>= 1) mx = fmaxf(mx, __shfl_xor_sync(0xffffffffu, mx, o));
    if (lane == 0) red[w] = mx;
    __syncthreads();
#pragma unroll
    for (int i = 0; i < 8; i++) mx = fmaxf(mx, red[i]);

    float s = 0.f;
#pragma unroll
    for (int i = 0; i < 8; i++) {
        v[i] = __expf(v[i] - mx);
        s += v[i];
    }
#pragma unroll
    for (int o = 16; o; o >>= 1) s += __shfl_xor_sync(0xffffffffu, s, o);
    __syncthreads();
    if (lane == 0) red[w] = s;
    __syncthreads();
    s = 0.f;
#pragma unroll
    for (int i = 0; i < 8; i++) s += red[i];
    const float inv = 1.f / s;
    if (tid == 0) sc[r] = inv * (1.0f / 127.0f);

    const int n    = (int)(r % SS);
    const int tile = n >> 7, rin = n & 127;
    char* pt = pan + ((r / SS) * 512 + (ll)tile * 32) * (ll)PAN;
#pragma unroll
    for (int i = 0; i < 8; i++) {
        const int c = tid + i * 256;
        const float pv = v[i] * inv;
        row[c] = pv;
        int8_t o1, o2;
        quant2(127.0f * v[i], o1, o2);
        char* pp = pt + (ll)(c >> 6) * PAN;
        const uint32_t off = pan_off(rin, c & 63);
        pp[off]        = o1;
        pp[8192 + off] = o2;
    }
}

// ---------------------------------------------------------------------------
// Launch
// ---------------------------------------------------------------------------
extern "C" void kernel_launch(void* const* d_in, const int* in_sizes, int n_in,
                              void* d_out, int out_size)
{
    (void)in_sizes; (void)n_in; (void)out_size;

    const float* hidden = (const float*)d_in[0];
    const float* mask   = (const float*)d_in[1];
    const int*   pos    = (const int*)  d_in[2];
    const float* Wq     = (const float*)d_in[3];
    const float* bq     = (const float*)d_in[4];
    const float* Wk     = (const float*)d_in[5];
    const float* bk     = (const float*)d_in[6];
    const float* Wv     = (const float*)d_in[7];
    const float* bv     = (const float*)d_in[8];
    const float* Wo     = (const float*)d_in[9];
    const float* bo     = (const float*)d_in[10];

    float* out  = (float*)d_out;                      // (B,S,HID)
    float* attn = out + (size_t)BB * SS * HID_;       // (B,H,S,S)

    float *qkv, *bqkv, *vT, *ctx;
    char *hidpan, *wqkvpan, *wopan, *qpan, *kpan, *vtpan, *attnpan, *ctxpan;
    float *sh, *sw, *swo, *sq, *sk, *svt, *sa, *sc;
    cudaGetSymbolAddress((void**)&qkv,     g_qkv);
    cudaGetSymbolAddress((void**)&bqkv,    g_bqkv);
    cudaGetSymbolAddress((void**)&vT,      g_vT);
    cudaGetSymbolAddress((void**)&ctx,     g_ctx);
    cudaGetSymbolAddress((void**)&hidpan,  g_hidpan);
    cudaGetSymbolAddress((void**)&wqkvpan, g_wqkvpan);
    cudaGetSymbolAddress((void**)&wopan,   g_wopan);
    cudaGetSymbolAddress((void**)&qpan,    g_qpan);
    cudaGetSymbolAddress((void**)&kpan,    g_kpan);
    cudaGetSymbolAddress((void**)&vtpan,   g_vtpan);
    cudaGetSymbolAddress((void**)&attnpan, g_attnpan);
    cudaGetSymbolAddress((void**)&ctxpan,  g_ctxpan);
    cudaGetSymbolAddress((void**)&sh,  g_sh);
    cudaGetSymbolAddress((void**)&sw,  g_sw);
    cudaGetSymbolAddress((void**)&swo, g_swo);
    cudaGetSymbolAddress((void**)&sq,  g_sq);
    cudaGetSymbolAddress((void**)&sk,  g_sk);
    cudaGetSymbolAddress((void**)&svt, g_svt);
    cudaGetSymbolAddress((void**)&sa,  g_sa);
    cudaGetSymbolAddress((void**)&sc,  g_sc);

    cudaFuncSetAttribute(igemm, cudaFuncAttributeMaxDynamicSharedMemorySize, GSMEM);

    const int M = BB * SS;   // 4096
    dim3 q256(256);
    dim3 g512(512);

    // 0) quantize + panelize inputs
    rowquant_pan<<<M,    q256>>>(hidden, HID_, 0,    hidpan, sh);
    rowquant_pan<<<2048, q256>>>(Wq,     HID_, 0,    wqkvpan, sw);
    rowquant_pan<<<256,  q256>>>(Wk,     HID_, 2048, wqkvpan, sw);
    rowquant_pan<<<256,  q256>>>(Wv,     HID_, 2304, wqkvpan, sw);
    rowquant_pan<<<2048, q256>>>(Wo,     HID_, 0,    wopan, swo);
    cudaMemcpyAsync(bqkv,        bq, 2048 * sizeof(float), cudaMemcpyDeviceToDevice);
    cudaMemcpyAsync(bqkv + 2048, bk,  256 * sizeof(float), cudaMemcpyDeviceToDevice);
    cudaMemcpyAsync(bqkv + 2304, bv,  256 * sizeof(float), cudaMemcpyDeviceToDevice);

    // 1) fused QKV projection (4096 x 2560 x 2048)
    igemm<<<dim3(NQKV / 128, M / 128, 1), g512, GSMEM>>>(
        hidpan, wqkvpan, sh, sw, bqkv, qkv,
        HID_, NQKV, 1,
        0, 0, 0, 0, 0, 0,
        0, 0, 1, 0, 0, 1, 1.0f);

    // 2) RoPE + quantize + panelize q (A panels), k (B panels)
    rope_quant_pan<<<BB * SS * HH, 128>>>(qkv,        pos, qpan, sq, HH);
    rope_quant_pan<<<BB * SS,      128>>>(qkv + 2048, pos, kpan, sk, 1);

    // 3) vT fp32 + quantize rows -> B panels
    transpose_v<<<dim3(SS / 32, DD / 32, BB), dim3(32, 8)>>>(qkv, vT);
    rowquant_pan<<<BB * DD, q256>>>(vT, SS, 0, vtpan, svt);

    // 4) scores = (q @ k^T)/16 -> attn fp32   (per bh: 2048x2048x256)
    igemm<<<dim3(SS / 128, SS / 128, BB * HH), g512, GSMEM>>>(
        qpan, kpan, sq, sk, nullptr, attn,
        DD, SS, HH,
        (ll)HH * 64 * PAN, (ll)64 * PAN,
        (ll)64 * PAN, 0,
        (ll)HH * SS * SS, (ll)SS * SS,
        (ll)SS * HH, 1, HH,
        (ll)SS, 0, 1,
        0.0625f);

    // 5) softmax in place (+mask) + quantized attn panels
    softmax_quant_pan<<<BB * HH * SS, q256>>>(attn, mask, attnpan, sa);

    // 6) ctx = attn @ v  (fp32)   (per bh: 2048x256x2048)
    igemm<<<dim3(DD / 128, SS / 128, BB * HH), g512, GSMEM>>>(
        attnpan, vtpan, sa, svt, nullptr, ctx,
        SS, HH * DD, HH,
        (ll)HH * 512 * PAN, (ll)512 * PAN,
        (ll)64 * PAN, 0,
        (ll)SS * HH * DD, (ll)DD,
        (ll)HH * SS, (ll)SS, 1,
        (ll)DD, 0, 1,
        1.0f);

    // 7) quantize ctx rows -> A panels
    rowquant_pan<<<M, q256>>>(ctx, HH * DD, 0, ctxpan, sc);

    // 8) out = ctx @ Wo^T + bo   (4096 x 2048 x 2048)
    igemm<<<dim3(HID_ / 128, M / 128, 1), g512, GSMEM>>>(
        ctxpan, wopan, sc, swo, bo, out,
        HH * DD, HID_, 1,
        0, 0, 0, 0, 0, 0,
        0, 0, 1, 0, 0, 1, 1.0f);
}

// round 15
// speedup vs baseline: 2.6089x; 2.6089x over previous
#include <cuda_runtime.h>
#include <cuda_bf16.h>
#include <math.h>
#include <stdint.h>

// Problem constants (Gemma attention, B=2,S=2048,HID=2048,H=8,KH=1,D=256)
#define BB   2
#define SS   2048
#define HID_ 2048
#define HH   8
#define DD   256
#define NQKV 2560

typedef __nv_bfloat16 bf16;
typedef __nv_bfloat162 bf162;
typedef long long ll;

// Panel: 128 rows x 32 k-elems bf16, hi 8KB | lo 8KB, SW64 swizzle.
#define PAN   16384
#define STG   (2 * PAN)          // A panel + B panel (each hi|lo)
#define NST   3
#define GSMEM (NST * STG)        // 98304 -> 2 CTAs/SM

// ---------------------------------------------------------------------------
// Scratch (__device__ globals — allocation-free)
// ---------------------------------------------------------------------------
__device__ float g_qkv[(size_t)BB * SS * NQKV];
__device__ float g_bqkv[NQKV];

__device__ __align__(128) char g_hidpan [(size_t)32 * 64 * PAN];          // 33.5 MB
__device__ __align__(128) char g_wqkvpan[(size_t)20 * 64 * PAN];          // 21 MB
__device__ __align__(128) char g_wopan  [(size_t)16 * 64 * PAN];          // 16.8 MB
__device__ __align__(128) char g_qpan   [(size_t)BB * HH * 16 * 8 * PAN]; // 33.5 MB
__device__ __align__(128) char g_kpan   [(size_t)BB * 16 * 8 * PAN];      // 4.2 MB
__device__ __align__(128) char g_vtpan  [(size_t)BB * 2 * 64 * PAN];      // 4.2 MB
__device__ __align__(128) char g_attnpan[(size_t)BB * HH * 16 * 64 * PAN];// 268 MB
__device__ __align__(128) char g_ctxpan [(size_t)32 * 64 * PAN];          // 33.5 MB

// ---------------------------------------------------------------------------
// PTX helpers
// ---------------------------------------------------------------------------
__device__ __forceinline__ uint32_t smem_u32(const void* p) {
    uint32_t a;
    asm("{ .reg .u64 t; cvta.to.shared.u64 t, %1; cvt.u32.u64 %0, t; }"
        : "=r"(a) : "l"(p));
    return a;
}

#define MBAR_INIT(addr, cnt) \
    asm volatile("mbarrier.init.shared.b64 [%0], %1;" :: "r"(addr), "r"(cnt) : "memory")
#define MBAR_ARRIVE(addr) \
    asm volatile("mbarrier.arrive.shared.b64 _, [%0];" :: "r"(addr) : "memory")
#define MBAR_EXPECT_TX(addr, bytes) \
    asm volatile("mbarrier.arrive.expect_tx.shared.b64 _, [%0], %1;" \
                 :: "r"(addr), "r"(bytes) : "memory")

#define WAITP(mbar_addr, parity) do {                                              \
    uint32_t _mbar = (uint32_t)(mbar_addr);                                        \
    uint32_t _par  = (uint32_t)(parity);                                           \
    uint32_t _done;                                                                \
    asm volatile(                                                                  \
        "{\n\t.reg .pred p;\n\t"                                                   \
        "mbarrier.try_wait.parity.acquire.cta.shared::cta.b64 p, [%1], %2;\n\t"    \
        "selp.b32 %0, 1, 0, p;\n\t}"                                               \
        : "=r"(_done) : "r"(_mbar), "r"(_par) : "memory");                         \
    if (!_done) {                                                                  \
        asm volatile(                                                              \
            "{\n\t.reg .pred P1;\n\t"                                              \
            "WAIT_LOOP_%=:\n\t"                                                    \
            "mbarrier.try_wait.parity.acquire.cta.shared::cta.b64 P1, [%0], %1, 0x989680;\n\t" \
            "@P1 bra.uni WAIT_DONE_%=;\n\t"                                        \
            "bra.uni WAIT_LOOP_%=;\n\t"                                            \
            "WAIT_DONE_%=:\n\t}"                                                   \
            :: "r"(_mbar), "r"(_par) : "memory");                                  \
    }                                                                              \
} while (0)

__device__ __forceinline__ void bulkcp(uint32_t dst, const void* src,
                                       uint32_t bytes, uint32_t mbar) {
    asm volatile(
        "cp.async.bulk.shared::cluster.global.mbarrier::complete_tx::bytes "
        "[%0], [%1], %2, [%3];"
        :: "r"(dst), "l"(src), "r"(bytes), "r"(mbar) : "memory");
}

__device__ __forceinline__ void ldm_x4(uint32_t* r, uint32_t addr) {
    asm volatile("ldmatrix.sync.aligned.m8n8.x4.shared.b16 {%0,%1,%2,%3}, [%4];"
                 : "=r"(r[0]), "=r"(r[1]), "=r"(r[2]), "=r"(r[3]) : "r"(addr));
}

__device__ __forceinline__ void mma_bf16(float* c, const uint32_t* a,
                                         uint32_t b0, uint32_t b1) {
    asm volatile(
        "mma.sync.aligned.m16n8k16.row.col.f32.bf16.bf16.f32 "
        "{%0,%1,%2,%3}, {%4,%5,%6,%7}, {%8,%9}, {%0,%1,%2,%3};"
        : "+f"(c[0]), "+f"(c[1]), "+f"(c[2]), "+f"(c[3])
        : "r"(a[0]), "r"(a[1]), "r"(a[2]), "r"(a[3]), "r"(b0), "r"(b1));
}

__device__ __forceinline__ void split1(float v, bf16& h, bf16& l) {
    h = __float2bfloat16(v);
    l = __float2bfloat16(v - __bfloat162float(h));
}

// SW64-swizzled byte offset of element (rin, cin) within a panel slice
// (128 rows x 64B rows, 16B segments, seg ^= (row>>1)&3). cin in bf16 elems.
__device__ __forceinline__ uint32_t pan_off(int rin, int cin) {
    return (uint32_t)(rin * 64 + ((((cin >> 3) ^ ((rin >> 1) & 3))) << 4)
                      + ((cin & 7) << 1));
}

// ===========================================================================
// Panelized split-bf16 NT GEMM on HMMA (3-pass error-compensated)
//   CTA tile 128x128xk32, 256 thr (8 warps, warp 64x32), 3-stage bulk-copy
//   pipeline, 2 CTAs/SM.
// ===========================================================================
__global__ __launch_bounds__(256, 2)
void pgemm(const char* __restrict__ Ap, const char* __restrict__ Bp,
           const float* __restrict__ bias, float* __restrict__ C,
           char* __restrict__ Cpan,
           int K, int ldc, int Hdim,
           ll sAb, ll sAh, ll sBb, ll sBh, ll sCb, ll sCh,
           ll pCb, ll pCh, ll pCy,
           float alpha)
{
    extern __shared__ __align__(128) char dsm[];
    __shared__ __align__(8) uint64_t mb[2 * NST];
    const uint32_t sbase = smem_u32(dsm);
    const uint32_t mbF = smem_u32(&mb[0]);
    const uint32_t mbE = smem_u32(&mb[NST]);

    const int tid  = threadIdx.x;
    const int wid  = tid >> 5;
    const int lane = tid & 31;
    const int wm   = wid >> 2;          // 0..1 (64-row band)
    const int wn   = wid & 3;           // 0..3 (32-col band)

    const int z  = blockIdx.z;
    const int bz = z / Hdim;
    const int hz = z - bz * Hdim;

    const int nc = K >> 5;
    const char* aSrc = Ap + (ll)bz * sAb + (ll)hz * sAh + (ll)blockIdx.y * nc * PAN;
    const char* bSrc = Bp + (ll)bz * sBb + (ll)hz * sBh + (ll)blockIdx.x * nc * PAN;

    if (tid == 0) {
#pragma unroll
        for (int s = 0; s < NST; s++) {
            MBAR_INIT(mbF + 8 * s, 1);
            MBAR_INIT(mbE + 8 * s, 256);
        }
    }
    __syncthreads();

    auto produce = [&](int c) {
        if (c >= nc || tid != 0) return;
        const int s = c % NST, r = c / NST;
        if (r > 0) WAITP(mbE + 8 * s, (r - 1) & 1);
        MBAR_EXPECT_TX(mbF + 8 * s, (uint32_t)STG);
        const uint32_t d = sbase + s * STG;
        bulkcp(d,       aSrc + (ll)c * PAN, PAN, mbF + 8 * s);
        bulkcp(d + PAN, bSrc + (ll)c * PAN, PAN, mbF + 8 * s);
    };

    float acc[4][4][4];
#pragma unroll
    for (int i = 0; i < 4; i++)
#pragma unroll
        for (int j = 0; j < 4; j++)
#pragma unroll
            for (int r = 0; r < 4; r++) acc[i][j][r] = 0.f;

    produce(0); produce(1); produce(2);

    const int rowloc = lane & 15;
    const int segb   = lane >> 4;
    const int xr     = (rowloc >> 1) & 3;

    for (int c = 0; c < nc; c++) {
        const int s = c % NST, r = c / NST;
        WAITP(mbF + 8 * s, r & 1);

        const uint32_t tb  = sbase + s * STG;
        const uint32_t aB0 = tb + wm * 4096;           // A hi: 8KB
        const uint32_t bB0 = tb + PAN + wn * 2048;     // B hi: 8KB

#pragma unroll
        for (int k16 = 0; k16 < 2; k16++) {
            const uint32_t lo = (uint32_t)rowloc * 64
                              + (uint32_t)(((segb + 2 * k16) ^ xr) << 4);
            uint32_t bH[2][4], bL[2][4];
#pragma unroll
            for (int nt = 0; nt < 2; nt++) {
                ldm_x4(bH[nt], bB0 + nt * 1024 + lo);
                ldm_x4(bL[nt], bB0 + 8192 + nt * 1024 + lo);
            }
#pragma unroll
            for (int mt = 0; mt < 4; mt++) {
                uint32_t aH[4], aL[4];
                ldm_x4(aH, aB0 + mt * 1024 + lo);
                ldm_x4(aL, aB0 + 8192 + mt * 1024 + lo);
#pragma unroll
                for (int j = 0; j < 4; j++)
                    mma_bf16(acc[mt][j], aH, bH[j >> 1][j & 1], bH[j >> 1][2 + (j & 1)]);
#pragma unroll
                for (int j = 0; j < 4; j++)
                    mma_bf16(acc[mt][j], aL, bH[j >> 1][j & 1], bH[j >> 1][2 + (j & 1)]);
#pragma unroll
                for (int j = 0; j < 4; j++)
                    mma_bf16(acc[mt][j], aH, bL[j >> 1][j & 1], bL[j >> 1][2 + (j & 1)]);
            }
        }
        MBAR_ARRIVE(mbE + 8 * s);
        produce(c + NST);
    }

    // ---- epilogue ----
    float* Cb = nullptr;
    if (C) Cb = C + (ll)bz * sCb + (ll)hz * sCh
              + (ll)blockIdx.y * 128 * ldc + (ll)blockIdx.x * 128;
    const ll pb0 = Cpan ? ((ll)bz * pCb + (ll)hz * pCh
                           + (ll)blockIdx.y * pCy + blockIdx.x * 4) : 0;
    const int colblk = blockIdx.x << 7;

#pragma unroll
    for (int mt = 0; mt < 4; mt++) {
        const int row0 = wm * 64 + mt * 16 + (lane >> 2);
#pragma unroll
        for (int hrow = 0; hrow < 2; hrow++) {
            const int row = row0 + hrow * 8;
#pragma unroll
            for (int j = 0; j < 4; j++) {
                const int col = wn * 32 + j * 8 + (lane & 3) * 2;
                float b0 = 0.f, b1 = 0.f;
                if (bias) { b0 = bias[colblk + col]; b1 = bias[colblk + col + 1]; }
                const float v0 = acc[mt][j][hrow * 2 + 0] * alpha + b0;
                const float v1 = acc[mt][j][hrow * 2 + 1] * alpha + b1;
                if (Cb) *(float2*)(Cb + (ll)row * ldc + col) = make_float2(v0, v1);
                if (Cpan) {
                    bf16 h0, l0, h1, l1;
                    split1(v0, h0, l0);
                    split1(v1, h1, l1);
                    char* p = Cpan + (pb0 + (col >> 5)) * (ll)PAN;
                    const uint32_t off = pan_off(row, col & 31);
                    *(bf162*)(p + off)        = __halves2bfloat162(h0, h1);
                    *(bf162*)(p + 8192 + off) = __halves2bfloat162(l0, l1);
                }
            }
        }
    }
}

// ---------------------------------------------------------------------------
// fp32 matrix (rows x C, row-major) -> split panels (tile rows T=128, hi|lo)
// ---------------------------------------------------------------------------
__global__ void split_panel(const float* __restrict__ x, char* __restrict__ pan,
                            int C, int row0, ll n)
{
    ll i = ((ll)blockIdx.x * blockDim.x + threadIdx.x) * 4;
    if (i >= n) return;
    float4 v = *(const float4*)(x + i);
    const int row = (int)(i / C) + row0;
    const int col = (int)(i % C);
    const int it = row >> 7, rin = row & 127;
    const int ic = col >> 5, cin = col & 31;
    char* p = pan + ((ll)it * (C >> 5) + ic) * (ll)PAN;
    const uint32_t off = pan_off(rin, cin);
    bf16 h0, l0, h1, l1, h2, l2, h3, l3;
    split1(v.x, h0, l0); split1(v.y, h1, l1);
    split1(v.z, h2, l2); split1(v.w, h3, l3);
    *(bf162*)(p + off)     = __halves2bfloat162(h0, h1);
    *(bf162*)(p + off + 4) = __halves2bfloat162(h2, h3);
    char* pl = p + 8192;
    *(bf162*)(pl + off)     = __halves2bfloat162(l0, l1);
    *(bf162*)(pl + off + 4) = __halves2bfloat162(l2, l3);
}

// ---------------------------------------------------------------------------
// RoPE + panelize: one block (128 thr) per (bs, h) row of 256 elems.
// Per (b*Hx+h): 16 tiles x 8 chunks.
// ---------------------------------------------------------------------------
__global__ __launch_bounds__(128)
void rope_pan(const float* __restrict__ src, const int* __restrict__ pos,
              char* __restrict__ pan, int Hx)
{
    const int blk = blockIdx.x;
    const int h   = blk % Hx;
    const int bs  = blk / Hx;
    const int b   = bs / SS, sI = bs % SS;
    const int t   = threadIdx.x;

    const float p   = (float)pos[bs];
    const float ivf = __expf(-(float)t * (9.210340371976184f / 128.f));
    float sn, cs;
    sincosf(p * ivf, &sn, &cs);
    const float* xr_ = src + (ll)bs * NQKV + h * DD;
    const float x1 = xr_[t], x2 = xr_[t + 128];
    const float y1 = cs * x1 - sn * x2;
    const float y2 = sn * x1 + cs * x2;

    const int it = sI >> 7, rin = sI & 127;
    char* pt = pan + (((ll)(b * Hx + h) * 16 + it) * 8) * (ll)PAN;
    bf16 hh, lv;
    {
        char* pp = pt + (ll)(t >> 5) * PAN;
        const uint32_t off = pan_off(rin, t & 31);
        split1(y1, hh, lv);
        *(bf16*)(pp + off)        = hh;
        *(bf16*)(pp + 8192 + off) = lv;
    }
    {
        const int d = t + 128;
        char* pp = pt + (ll)(d >> 5) * PAN;
        const uint32_t off = pan_off(rin, d & 31);
        split1(y2, hh, lv);
        *(bf16*)(pp + off)        = hh;
        *(bf16*)(pp + 8192 + off) = lv;
    }
}

// ---------------------------------------------------------------------------
// Transpose v (qkv col 2304) -> vT B-panels (per b: [ix in 2][ic in 64])
// ---------------------------------------------------------------------------
__global__ void transpose_pan(const float* __restrict__ qkv, char* __restrict__ pan)
{
    __shared__ float t[32][33];
    const int b  = blockIdx.z;
    const int s0 = blockIdx.x * 32;
    const int d0 = blockIdx.y * 32;
    const int tx = threadIdx.x, ty = threadIdx.y;
    const float* src = qkv + (ll)b * SS * NQKV + 2304;
#pragma unroll
    for (int i = 0; i < 32; i += 8)
        t[ty + i][tx] = src[(ll)(s0 + ty + i) * NQKV + d0 + tx];
    __syncthreads();
#pragma unroll
    for (int i = 0; i < 32; i += 8) {
        const int d  = d0 + ty + i;
        const int sI = s0 + tx;
        const int ix = d >> 7, rin = d & 127;
        const int ic = sI >> 5, cin = sI & 31;
        char* pp = pan + ((ll)(b * 2 + ix) * 64 + ic) * (ll)PAN;
        const uint32_t off = pan_off(rin, cin);
        bf16 h, l;
        split1(t[tx][ty + i], h, l);
        *(bf16*)(pp + off)        = h;
        *(bf16*)(pp + 8192 + off) = l;
    }
}

// ---------------------------------------------------------------------------
// Row softmax over attn (B,H,S,S) in place (+mask) + panelized split output
// Per (b,h): 16 tiles x 64 chunks.
// ---------------------------------------------------------------------------
__global__ __launch_bounds__(256)
void softmax_pan(float* __restrict__ attn, const float* __restrict__ mask,
                 char* __restrict__ pan)
{
    const int HSrows = HH * SS;
    const ll r = blockIdx.x;
    const int b = (int)(r / HSrows);
    float* row = attn + r * (ll)SS;
    const float* mrow = mask + (ll)b * SS;

    const int tid  = threadIdx.x;
    const int w    = tid >> 5;
    const int lane = tid & 31;
    __shared__ float red[8];

    float v[8];
    float mx = -1e30f;
#pragma unroll
    for (int i = 0; i < 8; i++) {
        const int c = tid + i * 256;
        const float x = row[c] + mrow[c];
        v[i] = x;
        mx = fmaxf(mx, x);
    }
#pragma unroll
    for (int o = 16; o; o >>= 1) mx = fmaxf(mx, __shfl_xor_sync(0xffffffffu, mx, o));
    if (lane == 0) red[w] = mx;
    __syncthreads();
#pragma unroll
    for (int i = 0; i < 8; i++) mx = fmaxf(mx, red[i]);

    float s = 0.f;
#pragma unroll
    for (int i = 0; i < 8; i++) {
        v[i] = __expf(v[i] - mx);
        s += v[i];
    }
#pragma unroll
    for (int o = 16; o; o >>= 1) s += __shfl_xor_sync(0xffffffffu, s, o);
    __syncthreads();
    if (lane == 0) red[w] = s;
    __syncthreads();
    s = 0.f;
#pragma unroll
    for (int i = 0; i < 8; i++) s += red[i];
    const float inv = 1.f / s;

    const int n    = (int)(r % SS);
    const int tile = n >> 7, rin = n & 127;
    char* pt = pan + ((r / SS) * 1024 + (ll)tile * 64) * (ll)PAN;
#pragma unroll
    for (int i = 0; i < 8; i++) {
        const int c = tid + i * 256;
        const float pv = v[i] * inv;
        row[c] = pv;
        bf16 h, l;
        split1(pv, h, l);
        char* pp = pt + (ll)(c >> 5) * PAN;
        const uint32_t off = pan_off(rin, c & 31);
        *(bf16*)(pp + off)        = h;
        *(bf16*)(pp + 8192 + off) = l;
    }
}

// ---------------------------------------------------------------------------
// Launch
// ---------------------------------------------------------------------------
extern "C" void kernel_launch(void* const* d_in, const int* in_sizes, int n_in,
                              void* d_out, int out_size)
{
    (void)in_sizes; (void)n_in; (void)out_size;

    const float* hidden = (const float*)d_in[0];
    const float* mask   = (const float*)d_in[1];
    const int*   pos    = (const int*)  d_in[2];
    const float* Wq     = (const float*)d_in[3];
    const float* bq     = (const float*)d_in[4];
    const float* Wk     = (const float*)d_in[5];
    const float* bk     = (const float*)d_in[6];
    const float* Wv     = (const float*)d_in[7];
    const float* bv     = (const float*)d_in[8];
    const float* Wo     = (const float*)d_in[9];
    const float* bo     = (const float*)d_in[10];

    float* out  = (float*)d_out;                      // (B,S,HID)
    float* attn = out + (size_t)BB * SS * HID_;       // (B,H,S,S)

    float *qkv, *bqkv;
    char *hidpan, *wqkvpan, *wopan, *qpan, *kpan, *vtpan, *attnpan, *ctxpan;
    cudaGetSymbolAddress((void**)&qkv,     g_qkv);
    cudaGetSymbolAddress((void**)&bqkv,    g_bqkv);
    cudaGetSymbolAddress((void**)&hidpan,  g_hidpan);
    cudaGetSymbolAddress((void**)&wqkvpan, g_wqkvpan);
    cudaGetSymbolAddress((void**)&wopan,   g_wopan);
    cudaGetSymbolAddress((void**)&qpan,    g_qpan);
    cudaGetSymbolAddress((void**)&kpan,    g_kpan);
    cudaGetSymbolAddress((void**)&vtpan,   g_vtpan);
    cudaGetSymbolAddress((void**)&attnpan, g_attnpan);
    cudaGetSymbolAddress((void**)&ctxpan,  g_ctxpan);

    cudaFuncSetAttribute(pgemm, cudaFuncAttributeMaxDynamicSharedMemorySize, GSMEM);

    const int M = BB * SS;   // 4096
    dim3 blk(256);

    // 0) panelize inputs
    {
        ll n = (ll)BB * SS * HID_;
        split_panel<<<(unsigned)((n / 4 + 255) / 256), blk>>>(hidden, hidpan, HID_, 0, n);
        n = (ll)HID_ * HID_;
        split_panel<<<(unsigned)((n / 4 + 255) / 256), blk>>>(Wq, wqkvpan, HID_, 0, n);
        n = (ll)DD * HID_;
        split_panel<<<(unsigned)((n / 4 + 255) / 256), blk>>>(Wk, wqkvpan, HID_, 2048, n);
        split_panel<<<(unsigned)((n / 4 + 255) / 256), blk>>>(Wv, wqkvpan, HID_, 2304, n);
        n = (ll)HID_ * HH * DD;
        split_panel<<<(unsigned)((n / 4 + 255) / 256), blk>>>(Wo, wopan, HID_, 0, n);
        cudaMemcpyAsync(bqkv,        bq, 2048 * sizeof(float), cudaMemcpyDeviceToDevice);
        cudaMemcpyAsync(bqkv + 2048, bk,  256 * sizeof(float), cudaMemcpyDeviceToDevice);
        cudaMemcpyAsync(bqkv + 2304, bv,  256 * sizeof(float), cudaMemcpyDeviceToDevice);
    }

    // 1) fused QKV projection: qkv = hidden @ Wqkv^T + bqkv  (4096 x 2560 x 2048)
    pgemm<<<dim3(NQKV / 128, M / 128, 1), blk, GSMEM>>>(
        hidpan, wqkvpan, bqkv, qkv, nullptr,
        HID_, NQKV, 1,
        0, 0, 0, 0, 0, 0,
        0, 0, 0, 1.0f);

    // 2) RoPE + panelize q (per-bh A panels), k (per-b B panels)
    rope_pan<<<BB * SS * HH, 128>>>(qkv,        pos, qpan, HH);
    rope_pan<<<BB * SS,      128>>>(qkv + 2048, pos, kpan, 1);

    // 3) vT B-panels
    transpose_pan<<<dim3(SS / 32, DD / 32, BB), dim3(32, 8)>>>(qkv, vtpan);

    // 4) scores = (q @ k^T)/16 -> attn fp32   (per bh: 2048x2048x256)
    pgemm<<<dim3(SS / 128, SS / 128, BB * HH), blk, GSMEM>>>(
        qpan, kpan, nullptr, attn, nullptr,
        DD, SS, HH,
        (ll)HH * 128 * PAN, (ll)128 * PAN,
        (ll)128 * PAN, 0,
        (ll)HH * SS * SS, (ll)SS * SS,
        0, 0, 0, 0.0625f);

    // 5) softmax in place (+mask) + panelized attn split
    softmax_pan<<<BB * HH * SS, blk>>>(attn, mask, attnpan);

    // 6) ctx = attn @ v -> ctx panels   (per bh: 2048x256x2048)
    pgemm<<<dim3(DD / 128, SS / 128, BB * HH), blk, GSMEM>>>(
        attnpan, vtpan, nullptr, nullptr, ctxpan,
        SS, 0, HH,
        (ll)HH * 1024 * PAN, (ll)1024 * PAN,
        (ll)128 * PAN, 0,
        0, 0,
        1024, 8, 64, 1.0f);

    // 7) out = ctx @ Wo^T + bo   (4096 x 2048 x 2048)
    pgemm<<<dim3(HID_ / 128, M / 128, 1), blk, GSMEM>>>(
        ctxpan, wopan, bo, out, nullptr,
        HH * DD, HID_, 1,
        0, 0, 0, 0, 0, 0,
        0, 0, 0, 1.0f);
}